// round 12
// baseline (speedup 1.0000x reference)
#include <cuda_runtime.h>
#include <math.h>
#include <stdint.h>

// Problem constants
#define BB   32
#define TS   64
#define TD   63
#define EE   256
#define UU   1024
#define G4   4096
#define VT   32000
#define GRID 128
#define NTHR 1024

// ---------------- device scratch ----------------
__device__ float g_EncPre[TS*BB*G4];
__device__ float g_DecPre[TD*BB*G4];
__device__ float g_mem [BB*TS*UU];     // [b][s][u]
__device__ float g_keys[BB*TS*UU];
__device__ float g_he[BB*UU], g_ce[BB*UU];
__device__ float g_hd[BB*UU], g_cd[BB*UU];
__device__ float g_attn[BB*UU], g_ctx[BB*UU];
__device__ float g_score[BB*TS];
__device__ float g_z[BB*G4];
__device__ float g_pab[4*BB*UU];
__device__ float g_attnAll[2048*UU];
__device__ unsigned g_bcount = 0;
__device__ unsigned g_bphase = 0;

__device__ __forceinline__ float sigmf(float x) { return 1.f / (1.f + expf(-x)); }
__device__ __forceinline__ uint32_t f2tf(float x) {
    uint32_t u; asm("cvt.rna.tf32.f32 %0, %1;" : "=r"(u) : "f"(x)); return u;
}
__device__ __forceinline__ unsigned ld_vol(const volatile unsigned* p) { return *p; }

// grid-wide barrier (all GRID blocks resident: grid<=148, 1 block/SM)
__device__ __forceinline__ void grid_sync(unsigned& tgt) {
    __syncthreads();
    if (threadIdx.x == 0) {
        __threadfence();
        unsigned old = atomicAdd(&g_bcount, 1);
        if (old == GRID - 1) {
            g_bcount = 0;
            __threadfence();
            atomicAdd(&g_bphase, 1);
        } else {
            while ((int)(ld_vol(&g_bphase) - tgt) < 0) { }
            __threadfence();
        }
    }
    __syncthreads();
    tgt++;
}

#define MMA_TF32(c0,c1,c2,c3,a0,a1,a2,a3,b0,b1) \
    asm volatile("mma.sync.aligned.m16n8k8.row.col.f32.tf32.tf32.f32 " \
        "{%0,%1,%2,%3}, {%4,%5,%6,%7}, {%8,%9}, {%0,%1,%2,%3};" \
        : "+f"(c0),"+f"(c1),"+f"(c2),"+f"(c3) \
        : "r"(a0),"r"(a1),"r"(a2),"r"(a3),"r"(b0),"r"(b1))

#define HS_STR 132
#define HP_STR 68
#define ZR_STR 33
#define SMEM_FLOATS (8*32*HS_STR + 8*32*ZR_STR)
#define SMEM_BYTES  (SMEM_FLOATS*4)

// stage A[32][1024] (fp32 global) into hs [8 kg][32 r][132]
__device__ __forceinline__ void stage_A1024(const float* __restrict__ A, float* hs) {
    const int tid = threadIdx.x;
#pragma unroll
    for (int i = 0; i < 8; i++) {
        int e = tid + i * NTHR;          // 8192 float4
        int r = e >> 8, k4 = e & 255;
        float4 v = *reinterpret_cast<const float4*>(A + r * UU + k4 * 4);
        int kgi = k4 >> 5, kk = (k4 & 31) * 4;
        *reinterpret_cast<float4*>(&hs[(kgi*32 + r)*HS_STR + kk]) = v;
    }
}

// one K=1024 tf32 mma pass: acc += A(hs) @ W[:, col0+0..31]; per-warp tile 32r x 8c
__device__ __forceinline__ void mma_pass(const float* hs, const float* __restrict__ W,
                                         int col0, int kg, int nw, int lane,
                                         float acc[2][4]) {
    const float* hsg = &hs[(kg*32)*HS_STR];
    const int r  = lane >> 2;
    const int bc = col0 + nw*8 + (lane >> 2);
#pragma unroll 4
    for (int k8 = 0; k8 < 16; k8++) {
        int kk = k8*8 + (lane & 3);
        uint32_t a0[4], a1[4];
        a0[0] = f2tf(hsg[ r      *HS_STR + kk]);   a0[1] = f2tf(hsg[(r+ 8)*HS_STR + kk]);
        a0[2] = f2tf(hsg[ r      *HS_STR + kk+4]); a0[3] = f2tf(hsg[(r+ 8)*HS_STR + kk+4]);
        a1[0] = f2tf(hsg[(r+16)*HS_STR + kk]);     a1[1] = f2tf(hsg[(r+24)*HS_STR + kk]);
        a1[2] = f2tf(hsg[(r+16)*HS_STR + kk+4]);   a1[3] = f2tf(hsg[(r+24)*HS_STR + kk+4]);
        int krow = kg*128 + k8*8 + (lane & 3);
        uint32_t b0 = f2tf(W[(size_t)krow     * G4 + bc]);
        uint32_t b1 = f2tf(W[(size_t)(krow+4) * G4 + bc]);
        MMA_TF32(acc[0][0],acc[0][1],acc[0][2],acc[0][3],
                 a0[0],a0[1],a0[2],a0[3], b0,b1);
        MMA_TF32(acc[1][0],acc[1][1],acc[1][2],acc[1][3],
                 a1[0],a1[1],a1[2],a1[3], b0,b1);
    }
}

// store per-warp acc into zr[kg][32][33]
__device__ __forceinline__ void acc_to_zr(float* zr, int kg, int nw, int lane,
                                          const float acc[2][4]) {
    int r = lane >> 2, cc = nw*8 + (lane & 3)*2;
    float* zk = &zr[(kg*32)*ZR_STR];
    zk[ r      *ZR_STR + cc] = acc[0][0]; zk[ r      *ZR_STR + cc+1] = acc[0][1];
    zk[(r+ 8)*ZR_STR + cc]   = acc[0][2]; zk[(r+ 8)*ZR_STR + cc+1]   = acc[0][3];
    zk[(r+16)*ZR_STR + cc]   = acc[1][0]; zk[(r+16)*ZR_STR + cc+1]   = acc[1][1];
    zk[(r+24)*ZR_STR + cc]   = acc[1][2]; zk[(r+24)*ZR_STR + cc+1]   = acc[1][3];
}

// ================= persistent encoder =================
__global__ void __launch_bounds__(NTHR, 1)
enc_persistent(const float* __restrict__ pre, const float* __restrict__ Whe,
               float* __restrict__ h, float* __restrict__ c,
               float* __restrict__ mem, float* __restrict__ z) {
    extern __shared__ float smem[];
    float* hs = smem;
    float* zr = smem + 8*32*HS_STR;
    __shared__ unsigned s_t0;
    const int tid = threadIdx.x, blk = blockIdx.x;
    const int warp = tid >> 5, lane = tid & 31;
    const int kg = warp >> 2, nw = warp & 3;
    const int col0 = blk * 32;
    if (tid == 0) s_t0 = ld_vol(&g_bphase) + 1;
    __syncthreads();
    unsigned tgt = s_t0;

    { int g = blk * NTHR + tid; if (g < BB*UU) { h[g] = 0.f; c[g] = 0.f; } }
    grid_sync(tgt);

    for (int t = 0; t < TS; t++) {
        stage_A1024(h, hs);
        __syncthreads();
        float acc[2][4] = {{0,0,0,0},{0,0,0,0}};
        mma_pass(hs, Whe, col0, kg, nw, lane, acc);
        __syncthreads();
        acc_to_zr(zr, kg, nw, lane, acc);
        __syncthreads();
        { int r = tid >> 5, cc = tid & 31;
          float s = 0.f;
#pragma unroll
          for (int q = 0; q < 8; q++) s += zr[(q*32 + r)*ZR_STR + cc];
          z[r*G4 + col0 + cc] = s; }
        grid_sync(tgt);
        if (tid < 256) {
            int g = blk*256 + tid, b = g >> 10, u = g & 1023;
            const float* pr = pre + ((size_t)t*BB + b)*G4;
            float zi = z[b*G4 + u]        + pr[u];
            float zf = z[b*G4 + 1024 + u] + pr[1024+u];
            float zg = z[b*G4 + 2048 + u] + pr[2048+u];
            float zo = z[b*G4 + 3072 + u] + pr[3072+u];
            float cn = sigmf(zf)*c[g] + sigmf(zi)*tanhf(zg);
            float hn = sigmf(zo)*tanhf(cn);
            c[g] = cn; h[g] = hn;
            mem[((size_t)b*TS + t)*UU + u] = hn;
        }
        grid_sync(tgt);
    }
}

// ================= persistent decoder =================
__global__ void __launch_bounds__(NTHR, 1)
dec_persistent(const float* __restrict__ pre,
               const float* __restrict__ Whd, const float* __restrict__ WxdA,
               const float* __restrict__ Wa,
               const float* __restrict__ keys, const float* __restrict__ mem,
               const float* __restrict__ he, const float* __restrict__ ce,
               float* __restrict__ hd, float* __restrict__ cd,
               float* __restrict__ attn, float* __restrict__ ctx,
               float* __restrict__ score, float* __restrict__ z,
               float* __restrict__ pab, float* __restrict__ attnAll) {
    extern __shared__ float smem[];
    float* hs = smem;
    float* zr = smem + 8*32*HS_STR;
    __shared__ float s_e[TS];
    __shared__ unsigned s_t0;
    const int tid = threadIdx.x, blk = blockIdx.x;
    const int warp = tid >> 5, lane = tid & 31;
    const int kg = warp >> 2, nw = warp & 3;
    if (tid == 0) s_t0 = ld_vol(&g_bphase) + 1;
    __syncthreads();
    unsigned tgt = s_t0;

    { int g = blk * NTHR + tid;
      if (g < BB*UU) { hd[g] = he[g]; cd[g] = ce[g]; attn[g] = 0.f; } }
    grid_sync(tgt);

    for (int t = 0; t < TD; t++) {
        // ---- z = pre + h@Whd + attn@WxdA ----
        const int col0 = blk * 32;
        float acc[2][4] = {{0,0,0,0},{0,0,0,0}};
        stage_A1024(hd, hs);
        __syncthreads();
        mma_pass(hs, Whd, col0, kg, nw, lane, acc);
        __syncthreads();
        stage_A1024(attn, hs);
        __syncthreads();
        mma_pass(hs, WxdA, col0, kg, nw, lane, acc);
        __syncthreads();
        acc_to_zr(zr, kg, nw, lane, acc);
        __syncthreads();
        { int r = tid >> 5, cc = tid & 31;
          float s = 0.f;
#pragma unroll
          for (int q = 0; q < 8; q++) s += zr[(q*32 + r)*ZR_STR + cc];
          z[r*G4 + col0 + cc] = s; }
        grid_sync(tgt);
        // ---- gates ----
        if (tid < 256) {
            int g = blk*256 + tid, b = g >> 10, u = g & 1023;
            const float* pr = pre + ((size_t)t*BB + b)*G4;
            float zi = z[b*G4 + u]        + pr[u];
            float zf = z[b*G4 + 1024 + u] + pr[1024+u];
            float zg = z[b*G4 + 2048 + u] + pr[2048+u];
            float zo = z[b*G4 + 3072 + u] + pr[3072+u];
            float cn = sigmf(zf)*cd[g] + sigmf(zi)*tanhf(zg);
            float hn = sigmf(zo)*tanhf(cn);
            cd[g] = cn; hd[g] = hn;
        }
        grid_sync(tgt);
        // ---- scores: 2048 (b,s) dots, warp each ----
        if (warp < 16) {
            int p = blk*16 + warp;
            int b = p >> 6, s = p & 63;
            const float* hp = hd + b*UU;
            const float* kp = keys + ((size_t)b*TS + s)*UU;
            float a = 0.f;
#pragma unroll 8
            for (int k = lane; k < UU; k += 32) a += hp[k] * kp[k];
#pragma unroll
            for (int o = 16; o; o >>= 1) a += __shfl_down_sync(0xffffffffu, a, o);
            if (lane == 0) score[p] = a;
        }
        grid_sync(tgt);
        // ---- softmax + context: one b per block ----
        {
            int b = blk >> 2;
            if (tid < TS) s_e[tid] = score[b*TS + tid];
            __syncthreads();
            float m = s_e[0];
#pragma unroll
            for (int s = 1; s < TS; s++) m = fmaxf(m, s_e[s]);
            __syncthreads();
            if (tid < TS) s_e[tid] = expf(s_e[tid] - m);
            __syncthreads();
            float tot = 0.f;
#pragma unroll
            for (int s = 0; s < TS; s++) tot += s_e[s];
            if (tid < 256) {
                int u = (blk & 3) * 256 + tid;
                float a = 0.f;
#pragma unroll 8
                for (int s = 0; s < TS; s++)
                    a += s_e[s] * mem[((size_t)b*TS + s)*UU + u];
                ctx[b*UU + u] = a / tot;
            }
        }
        grid_sync(tgt);
        // ---- attn = [h;ctx] @ Wa : block = (kq 0..3) x (ct 0..31) ----
        {
            const int ct = blk & 31, kq = blk >> 5;
#pragma unroll
            for (int i = 0; i < 4; i++) {
                int e = tid + i * NTHR;         // 4096 float4
                int r = e >> 7, k4 = e & 127;
                int ka4 = kq*128 + k4;
                float4 v = (ka4 < 256)
                    ? *reinterpret_cast<const float4*>(hd  + r*UU + ka4*4)
                    : *reinterpret_cast<const float4*>(ctx + r*UU + (ka4-256)*4);
                int kgi = k4 >> 4, kk = (k4 & 15) * 4;
                *reinterpret_cast<float4*>(&hs[(kgi*32 + r)*HP_STR + kk]) = v;
            }
            __syncthreads();
            float pa[2][4] = {{0,0,0,0},{0,0,0,0}};
            const float* hsg = &hs[(kg*32)*HP_STR];
            const int r  = lane >> 2;
            const int bc = ct*32 + nw*8 + (lane >> 2);
#pragma unroll
            for (int k8 = 0; k8 < 8; k8++) {
                int kk = k8*8 + (lane & 3);
                uint32_t a0[4], a1[4];
                a0[0] = f2tf(hsg[ r      *HP_STR + kk]);   a0[1] = f2tf(hsg[(r+ 8)*HP_STR + kk]);
                a0[2] = f2tf(hsg[ r      *HP_STR + kk+4]); a0[3] = f2tf(hsg[(r+ 8)*HP_STR + kk+4]);
                a1[0] = f2tf(hsg[(r+16)*HP_STR + kk]);     a1[1] = f2tf(hsg[(r+24)*HP_STR + kk]);
                a1[2] = f2tf(hsg[(r+16)*HP_STR + kk+4]);   a1[3] = f2tf(hsg[(r+24)*HP_STR + kk+4]);
                int krow = kq*512 + kg*64 + k8*8 + (lane & 3);
                uint32_t b0 = f2tf(Wa[(size_t)krow     * UU + bc]);
                uint32_t b1 = f2tf(Wa[(size_t)(krow+4) * UU + bc]);
                MMA_TF32(pa[0][0],pa[0][1],pa[0][2],pa[0][3],
                         a0[0],a0[1],a0[2],a0[3], b0,b1);
                MMA_TF32(pa[1][0],pa[1][1],pa[1][2],pa[1][3],
                         a1[0],a1[1],a1[2],a1[3], b0,b1);
            }
            __syncthreads();
            acc_to_zr(zr, kg, nw, lane, pa);
            __syncthreads();
            { int r2 = tid >> 5, cc = tid & 31;
              float s = 0.f;
#pragma unroll
              for (int q = 0; q < 8; q++) s += zr[(q*32 + r2)*ZR_STR + cc];
              pab[((size_t)kq*BB + r2)*UU + ct*32 + cc] = s; }
        }
        grid_sync(tgt);
        // ---- reduce partials -> attn, attnAll ----
        if (tid < 256) {
            int g = blk*256 + tid, b = g >> 10, u = g & 1023;
            float v = pab[((size_t)0*BB + b)*UU + u] + pab[((size_t)1*BB + b)*UU + u]
                    + pab[((size_t)2*BB + b)*UU + u] + pab[((size_t)3*BB + b)*UU + u];
            attn[g] = v;
            attnAll[((size_t)t*BB + b)*UU + u] = v;
        }
        grid_sync(tgt);
    }
}

// ---------------- embedding-gathered pre GEMM (one-shot) ----------------
__global__ void __launch_bounds__(128) pre_gemm(const int* __restrict__ ids, int T,
                                                const float* __restrict__ emb,
                                                const float* __restrict__ W,
                                                const float* __restrict__ bias,
                                                float* __restrict__ out) {
    __shared__ __align__(16) float As[32*36];
    __shared__ int sid[32];
    const int tid = threadIdx.x;
    const int t   = blockIdx.y;
    const int col = blockIdx.x * 128 + tid;
    if (tid < 32) sid[tid] = ids[tid * T + t];
    __syncthreads();
    float acc[32];
#pragma unroll
    for (int r = 0; r < 32; r++) acc[r] = 0.f;
    for (int kk = 0; kk < EE; kk += 32) {
#pragma unroll
        for (int i = 0; i < 8; i++) {
            int e = tid + i * 128;
            int j = e & 31, r = e >> 5;
            As[j*36 + r] = emb[sid[r]*EE + kk + j];
        }
        __syncthreads();
#pragma unroll 4
        for (int j = 0; j < 32; j++) {
            float w = W[(kk + j) * G4 + col];
#pragma unroll
            for (int q = 0; q < 8; q++) {
                float4 a = *reinterpret_cast<const float4*>(&As[j*36 + q*4]);
                acc[q*4+0] += a.x*w; acc[q*4+1] += a.y*w;
                acc[q*4+2] += a.z*w; acc[q*4+3] += a.w*w;
            }
        }
        __syncthreads();
    }
    float bb = bias[col];
    float* o = out + t * 32 * G4 + col;
#pragma unroll
    for (int r = 0; r < 32; r++) o[r * G4] = acc[r] + bb;
}

// ---------------- full-K skinny GEMM (keys, one-shot) ----------------
__global__ void __launch_bounds__(128) fullk32_gemm(const float* __restrict__ A_,
                                                    const float* __restrict__ W,
                                                    float* __restrict__ out, int N) {
    __shared__ __align__(16) float As[32*36];
    const int tid = threadIdx.x;
    const int col = blockIdx.x * 128 + tid;
    const float* A = A_ + (size_t)blockIdx.y * 32 * UU;
    float acc[32];
#pragma unroll
    for (int r = 0; r < 32; r++) acc[r] = 0.f;
    for (int kk = 0; kk < UU; kk += 32) {
#pragma unroll
        for (int i = 0; i < 8; i++) {
            int e = tid + i * 128;
            int j = e & 31, r = e >> 5;
            As[j*36 + r] = A[r * UU + kk + j];
        }
        __syncthreads();
#pragma unroll 4
        for (int j = 0; j < 32; j++) {
            float w = W[(kk + j) * N + col];
#pragma unroll
            for (int q = 0; q < 8; q++) {
                float4 a = *reinterpret_cast<const float4*>(&As[j*36 + q*4]);
                acc[q*4+0] += a.x*w; acc[q*4+1] += a.y*w;
                acc[q*4+2] += a.z*w; acc[q*4+3] += a.w*w;
            }
        }
        __syncthreads();
    }
    float* o = out + (size_t)blockIdx.y * 32 * N + col;
#pragma unroll
    for (int r = 0; r < 32; r++) o[r * N] = acc[r];
}

// ---------------- final logits GEMM: tf32 mma, 128x128 tile ----------------
#define KC 32
__global__ void __launch_bounds__(256) final_mma(const float* __restrict__ A,
                                                 const float* __restrict__ Wf,
                                                 const float* __restrict__ bf,
                                                 float* __restrict__ out) {
    const int m0 = blockIdx.x * 128;
    const int n0 = blockIdx.y * 128;
    const int tid = threadIdx.x, lane = tid & 31, warp = tid >> 5;
    const int wm = warp >> 1;
    const int wn = warp & 1;
    __shared__ uint32_t Asm[128][KC + 1];
    __shared__ uint32_t Bsm[KC][128 + 8];
    float acc[2][8][4];
#pragma unroll
    for (int mi = 0; mi < 2; mi++)
#pragma unroll
        for (int nf = 0; nf < 8; nf++)
#pragma unroll
            for (int i = 0; i < 4; i++) acc[mi][nf][i] = 0.f;

    for (int k0 = 0; k0 < UU; k0 += KC) {
#pragma unroll
        for (int i = 0; i < 4; i++) {
            int e = tid + i * 256;
            int r = e >> 3, c = (e & 7) * 4;
            float4 v = *reinterpret_cast<const float4*>(A + (size_t)(m0 + r) * UU + k0 + c);
            Asm[r][c] = f2tf(v.x); Asm[r][c+1] = f2tf(v.y);
            Asm[r][c+2] = f2tf(v.z); Asm[r][c+3] = f2tf(v.w);
        }
#pragma unroll
        for (int i = 0; i < 4; i++) {
            int e = tid + i * 256;
            int r = e >> 5, c = (e & 31) * 4;
            float4 v = *reinterpret_cast<const float4*>(Wf + (size_t)(k0 + r) * VT + n0 + c);
            Bsm[r][c] = f2tf(v.x); Bsm[r][c+1] = f2tf(v.y);
            Bsm[r][c+2] = f2tf(v.z); Bsm[r][c+3] = f2tf(v.w);
        }
        __syncthreads();
#pragma unroll
        for (int k8 = 0; k8 < 4; k8++) {
            const int kb = k8 * 8;
            uint32_t af[2][4];
#pragma unroll
            for (int mi = 0; mi < 2; mi++) {
                int ar = 32 * wm + 16 * mi + (lane >> 2);
                int ac = kb + (lane & 3);
                af[mi][0] = Asm[ar][ac];     af[mi][1] = Asm[ar + 8][ac];
                af[mi][2] = Asm[ar][ac + 4]; af[mi][3] = Asm[ar + 8][ac + 4];
            }
#pragma unroll
            for (int nf = 0; nf < 8; nf++) {
                int bc = 64 * wn + nf * 8 + (lane >> 2);
                int br = kb + (lane & 3);
                uint32_t b0 = Bsm[br][bc], b1 = Bsm[br + 4][bc];
#pragma unroll
                for (int mi = 0; mi < 2; mi++) {
                    MMA_TF32(acc[mi][nf][0], acc[mi][nf][1], acc[mi][nf][2], acc[mi][nf][3],
                             af[mi][0], af[mi][1], af[mi][2], af[mi][3], b0, b1);
                }
            }
        }
        __syncthreads();
    }
#pragma unroll
    for (int mi = 0; mi < 2; mi++) {
#pragma unroll
        for (int nf = 0; nf < 8; nf++) {
            int col = n0 + 64 * wn + nf * 8 + (lane & 3) * 2;
            float bb0 = bf[col], bb1 = bf[col + 1];
#pragma unroll
            for (int hh = 0; hh < 2; hh++) {
                int m = m0 + 32 * wm + 16 * mi + (lane >> 2) + 8 * hh;
                if (m < TD * BB) {
                    int b = m & 31, t = m >> 5;
                    float* o = out + ((size_t)(b * TD + t)) * VT + col;
                    o[0] = acc[mi][nf][2*hh + 0] + bb0;
                    o[1] = acc[mi][nf][2*hh + 1] + bb1;
                }
            }
        }
    }
}

// ---------------- host ----------------
extern "C" void kernel_launch(void* const* d_in, const int* in_sizes, int n_in,
                              void* d_out, int out_size) {
    const int*   enc_in  = (const int*)  d_in[0];
    const int*   dec_in  = (const int*)  d_in[1];
    const float* enc_emb = (const float*)d_in[2];
    const float* dec_emb = (const float*)d_in[3];
    const float* Wx_e    = (const float*)d_in[4];
    const float* Wh_e    = (const float*)d_in[5];
    const float* b_e     = (const float*)d_in[6];
    const float* Wx_d    = (const float*)d_in[7];
    const float* Wh_d    = (const float*)d_in[8];
    const float* b_d     = (const float*)d_in[9];
    const float* Wm      = (const float*)d_in[10];
    const float* Wa      = (const float*)d_in[11];
    const float* Wf      = (const float*)d_in[12];
    const float* bf      = (const float*)d_in[13];
    float* out = (float*)d_out;

    float *pEncPre, *pDecPre, *pMem, *pKeys, *pHe, *pCe, *pHd, *pCd;
    float *pAttn, *pCtx, *pScore, *pZ, *pPab, *pAll;
    cudaGetSymbolAddress((void**)&pEncPre, g_EncPre);
    cudaGetSymbolAddress((void**)&pDecPre, g_DecPre);
    cudaGetSymbolAddress((void**)&pMem,    g_mem);
    cudaGetSymbolAddress((void**)&pKeys,   g_keys);
    cudaGetSymbolAddress((void**)&pHe,     g_he);
    cudaGetSymbolAddress((void**)&pCe,     g_ce);
    cudaGetSymbolAddress((void**)&pHd,     g_hd);
    cudaGetSymbolAddress((void**)&pCd,     g_cd);
    cudaGetSymbolAddress((void**)&pAttn,   g_attn);
    cudaGetSymbolAddress((void**)&pCtx,    g_ctx);
    cudaGetSymbolAddress((void**)&pScore,  g_score);
    cudaGetSymbolAddress((void**)&pZ,      g_z);
    cudaGetSymbolAddress((void**)&pPab,    g_pab);
    cudaGetSymbolAddress((void**)&pAll,    g_attnAll);

    cudaFuncSetAttribute(enc_persistent, cudaFuncAttributeMaxDynamicSharedMemorySize, SMEM_BYTES);
    cudaFuncSetAttribute(dec_persistent, cudaFuncAttributeMaxDynamicSharedMemorySize, SMEM_BYTES);

    // one-shot input projections
    pre_gemm<<<dim3(32, TS), 128>>>(enc_in, TS, enc_emb, Wx_e, b_e, pEncPre);
    pre_gemm<<<dim3(32, TD), 128>>>(dec_in, TD, dec_emb, Wx_d, b_d, pDecPre);

    // persistent encoder recurrence
    enc_persistent<<<GRID, NTHR, SMEM_BYTES>>>(pEncPre, Wh_e, pHe, pCe, pMem, pZ);

    // attention keys
    fullk32_gemm<<<dim3(8, 64), 128>>>(pMem, Wm, pKeys, UU);

    // persistent decoder recurrence
    dec_persistent<<<GRID, NTHR, SMEM_BYTES>>>(pDecPre, Wh_d, Wx_d + 256*G4, Wa,
                                               pKeys, pMem, pHe, pCe, pHd, pCd,
                                               pAttn, pCtx, pScore, pZ, pPab, pAll);

    // batched logits GEMM
    final_mma<<<dim3(16, VT / 128), 256>>>(pAll, Wf, bf, out);
}

// round 13
// speedup vs baseline: 1.0047x; 1.0047x over previous
#include <cuda_runtime.h>
#include <math.h>
#include <stdint.h>

// Problem constants
#define BB   32
#define TS   64
#define TD   63
#define EE   256
#define UU   1024
#define G4   4096
#define VT   32000
#define GRID 128
#define NTHR 1024

// ---------------- device scratch ----------------
__device__ float g_EncPre[TS*BB*G4];
__device__ float g_DecPre[TD*BB*G4];
__device__ float g_mem [BB*TS*UU];     // [b][s][u]
__device__ float g_keys[BB*TS*UU];
__device__ float g_he[BB*UU], g_ce[BB*UU];
__device__ float g_hd[BB*UU], g_cd[BB*UU];
__device__ float g_attn[BB*UU], g_ctx[BB*UU];
__device__ float g_score[BB*TS];
__device__ float g_z[BB*G4];
__device__ float g_pab[4*BB*UU];
__device__ float g_attnAll[2048*UU];
__device__ unsigned g_bcount = 0;
__device__ unsigned g_bphase = 0;

__device__ __forceinline__ float sigmf(float x) { return 1.f / (1.f + expf(-x)); }
__device__ __forceinline__ uint32_t f2tf(float x) {
    uint32_t u; asm("cvt.rna.tf32.f32 %0, %1;" : "=r"(u) : "f"(x)); return u;
}
__device__ __forceinline__ unsigned ld_vol(const volatile unsigned* p) { return *p; }

// grid-wide barrier (all GRID blocks resident: grid<=148, 1 block/SM)
__device__ __forceinline__ void grid_sync(unsigned& tgt) {
    __syncthreads();
    if (threadIdx.x == 0) {
        __threadfence();
        unsigned old = atomicAdd(&g_bcount, 1);
        if (old == GRID - 1) {
            g_bcount = 0;
            __threadfence();
            atomicAdd(&g_bphase, 1);
        } else {
            while ((int)(ld_vol(&g_bphase) - tgt) < 0) { }
            __threadfence();
        }
    }
    __syncthreads();
    tgt++;
}

#define MMA_TF32(c0,c1,c2,c3,a0,a1,a2,a3,b0,b1) \
    asm volatile("mma.sync.aligned.m16n8k8.row.col.f32.tf32.tf32.f32 " \
        "{%0,%1,%2,%3}, {%4,%5,%6,%7}, {%8,%9}, {%0,%1,%2,%3};" \
        : "+f"(c0),"+f"(c1),"+f"(c2),"+f"(c3) \
        : "r"(a0),"r"(a1),"r"(a2),"r"(a3),"r"(b0),"r"(b1))

#define HS_STR 132
#define HP_STR 68
#define ZR_STR 33
#define SMEM_FLOATS (8*32*HS_STR + 8*32*ZR_STR)
#define SMEM_BYTES  (SMEM_FLOATS*4)

// stage A[32][1024] (fp32 global) into hs [8 kg][32 r][132]
__device__ __forceinline__ void stage_A1024(const float* __restrict__ A, float* hs) {
    const int tid = threadIdx.x;
#pragma unroll
    for (int i = 0; i < 8; i++) {
        int e = tid + i * NTHR;          // 8192 float4
        int r = e >> 8, k4 = e & 255;
        float4 v = *reinterpret_cast<const float4*>(A + r * UU + k4 * 4);
        int kgi = k4 >> 5, kk = (k4 & 31) * 4;
        *reinterpret_cast<float4*>(&hs[(kgi*32 + r)*HS_STR + kk]) = v;
    }
}

// one K=1024 tf32 mma pass: acc += A(hs) @ W[:, col0+0..31]; per-warp tile 32r x 8c
__device__ __forceinline__ void mma_pass(const float* hs, const float* __restrict__ W,
                                         int col0, int kg, int nw, int lane,
                                         float acc[2][4]) {
    const float* hsg = &hs[(kg*32)*HS_STR];
    const int r  = lane >> 2;
    const int bc = col0 + nw*8 + (lane >> 2);
#pragma unroll 4
    for (int k8 = 0; k8 < 16; k8++) {
        int kk = k8*8 + (lane & 3);
        uint32_t a0[4], a1[4];
        a0[0] = f2tf(hsg[ r      *HS_STR + kk]);   a0[1] = f2tf(hsg[(r+ 8)*HS_STR + kk]);
        a0[2] = f2tf(hsg[ r      *HS_STR + kk+4]); a0[3] = f2tf(hsg[(r+ 8)*HS_STR + kk+4]);
        a1[0] = f2tf(hsg[(r+16)*HS_STR + kk]);     a1[1] = f2tf(hsg[(r+24)*HS_STR + kk]);
        a1[2] = f2tf(hsg[(r+16)*HS_STR + kk+4]);   a1[3] = f2tf(hsg[(r+24)*HS_STR + kk+4]);
        int krow = kg*128 + k8*8 + (lane & 3);
        uint32_t b0 = f2tf(W[(size_t)krow     * G4 + bc]);
        uint32_t b1 = f2tf(W[(size_t)(krow+4) * G4 + bc]);
        MMA_TF32(acc[0][0],acc[0][1],acc[0][2],acc[0][3],
                 a0[0],a0[1],a0[2],a0[3], b0,b1);
        MMA_TF32(acc[1][0],acc[1][1],acc[1][2],acc[1][3],
                 a1[0],a1[1],a1[2],a1[3], b0,b1);
    }
}

// store per-warp acc into zr[kg][32][33]
__device__ __forceinline__ void acc_to_zr(float* zr, int kg, int nw, int lane,
                                          const float acc[2][4]) {
    int r = lane >> 2, cc = nw*8 + (lane & 3)*2;
    float* zk = &zr[(kg*32)*ZR_STR];
    zk[ r      *ZR_STR + cc] = acc[0][0]; zk[ r      *ZR_STR + cc+1] = acc[0][1];
    zk[(r+ 8)*ZR_STR + cc]   = acc[0][2]; zk[(r+ 8)*ZR_STR + cc+1]   = acc[0][3];
    zk[(r+16)*ZR_STR + cc]   = acc[1][0]; zk[(r+16)*ZR_STR + cc+1]   = acc[1][1];
    zk[(r+24)*ZR_STR + cc]   = acc[1][2]; zk[(r+24)*ZR_STR + cc+1]   = acc[1][3];
}

// ================= persistent encoder =================
__global__ void __launch_bounds__(NTHR, 1)
enc_persistent(const float* __restrict__ pre, const float* __restrict__ Whe,
               float* __restrict__ h, float* __restrict__ c,
               float* __restrict__ mem, float* __restrict__ z) {
    extern __shared__ float smem[];
    float* hs = smem;
    float* zr = smem + 8*32*HS_STR;
    __shared__ unsigned s_t0;
    const int tid = threadIdx.x, blk = blockIdx.x;
    const int warp = tid >> 5, lane = tid & 31;
    const int kg = warp >> 2, nw = warp & 3;
    const int col0 = blk * 32;
    if (tid == 0) s_t0 = ld_vol(&g_bphase) + 1;
    __syncthreads();
    unsigned tgt = s_t0;

    { int g = blk * NTHR + tid; if (g < BB*UU) { h[g] = 0.f; c[g] = 0.f; } }
    grid_sync(tgt);

    for (int t = 0; t < TS; t++) {
        stage_A1024(h, hs);
        __syncthreads();
        float acc[2][4] = {{0,0,0,0},{0,0,0,0}};
        mma_pass(hs, Whe, col0, kg, nw, lane, acc);
        __syncthreads();
        acc_to_zr(zr, kg, nw, lane, acc);
        __syncthreads();
        { int r = tid >> 5, cc = tid & 31;
          float s = 0.f;
#pragma unroll
          for (int q = 0; q < 8; q++) s += zr[(q*32 + r)*ZR_STR + cc];
          z[r*G4 + col0 + cc] = s; }
        grid_sync(tgt);
        if (tid < 256) {
            int g = blk*256 + tid, b = g >> 10, u = g & 1023;
            const float* pr = pre + ((size_t)t*BB + b)*G4;
            float zi = z[b*G4 + u]        + pr[u];
            float zf = z[b*G4 + 1024 + u] + pr[1024+u];
            float zg = z[b*G4 + 2048 + u] + pr[2048+u];
            float zo = z[b*G4 + 3072 + u] + pr[3072+u];
            float cn = sigmf(zf)*c[g] + sigmf(zi)*tanhf(zg);
            float hn = sigmf(zo)*tanhf(cn);
            c[g] = cn; h[g] = hn;
            mem[((size_t)b*TS + t)*UU + u] = hn;
        }
        grid_sync(tgt);
    }
}

// ================= persistent decoder =================
__global__ void __launch_bounds__(NTHR, 1)
dec_persistent(const float* __restrict__ pre,
               const float* __restrict__ Whd, const float* __restrict__ WxdA,
               const float* __restrict__ Wa,
               const float* __restrict__ keys, const float* __restrict__ mem,
               const float* __restrict__ he, const float* __restrict__ ce,
               float* __restrict__ hd, float* __restrict__ cd,
               float* __restrict__ attn, float* __restrict__ ctx,
               float* __restrict__ score, float* __restrict__ z,
               float* __restrict__ pab, float* __restrict__ attnAll) {
    extern __shared__ float smem[];
    float* hs = smem;
    float* zr = smem + 8*32*HS_STR;
    __shared__ float s_e[TS];
    __shared__ unsigned s_t0;
    const int tid = threadIdx.x, blk = blockIdx.x;
    const int warp = tid >> 5, lane = tid & 31;
    const int kg = warp >> 2, nw = warp & 3;
    if (tid == 0) s_t0 = ld_vol(&g_bphase) + 1;
    __syncthreads();
    unsigned tgt = s_t0;

    { int g = blk * NTHR + tid;
      if (g < BB*UU) { hd[g] = he[g]; cd[g] = ce[g]; attn[g] = 0.f; } }
    grid_sync(tgt);

    for (int t = 0; t < TD; t++) {
        // ---- z = pre + h@Whd + attn@WxdA ----
        const int col0 = blk * 32;
        float acc[2][4] = {{0,0,0,0},{0,0,0,0}};
        stage_A1024(hd, hs);
        __syncthreads();
        mma_pass(hs, Whd, col0, kg, nw, lane, acc);
        __syncthreads();
        stage_A1024(attn, hs);
        __syncthreads();
        mma_pass(hs, WxdA, col0, kg, nw, lane, acc);
        __syncthreads();
        acc_to_zr(zr, kg, nw, lane, acc);
        __syncthreads();
        { int r = tid >> 5, cc = tid & 31;
          float s = 0.f;
#pragma unroll
          for (int q = 0; q < 8; q++) s += zr[(q*32 + r)*ZR_STR + cc];
          z[r*G4 + col0 + cc] = s; }
        grid_sync(tgt);
        // ---- gates ----
        if (tid < 256) {
            int g = blk*256 + tid, b = g >> 10, u = g & 1023;
            const float* pr = pre + ((size_t)t*BB + b)*G4;
            float zi = z[b*G4 + u]        + pr[u];
            float zf = z[b*G4 + 1024 + u] + pr[1024+u];
            float zg = z[b*G4 + 2048 + u] + pr[2048+u];
            float zo = z[b*G4 + 3072 + u] + pr[3072+u];
            float cn = sigmf(zf)*cd[g] + sigmf(zi)*tanhf(zg);
            float hn = sigmf(zo)*tanhf(cn);
            cd[g] = cn; hd[g] = hn;
        }
        grid_sync(tgt);
        // ---- scores: 2048 (b,s) dots, warp each ----
        if (warp < 16) {
            int p = blk*16 + warp;
            int b = p >> 6, s = p & 63;
            const float* hp = hd + b*UU;
            const float* kp = keys + ((size_t)b*TS + s)*UU;
            float a = 0.f;
#pragma unroll 8
            for (int k = lane; k < UU; k += 32) a += hp[k] * kp[k];
#pragma unroll
            for (int o = 16; o; o >>= 1) a += __shfl_down_sync(0xffffffffu, a, o);
            if (lane == 0) score[p] = a;
        }
        grid_sync(tgt);
        // ---- softmax + context: one b per block ----
        {
            int b = blk >> 2;
            if (tid < TS) s_e[tid] = score[b*TS + tid];
            __syncthreads();
            float m = s_e[0];
#pragma unroll
            for (int s = 1; s < TS; s++) m = fmaxf(m, s_e[s]);
            __syncthreads();
            if (tid < TS) s_e[tid] = expf(s_e[tid] - m);
            __syncthreads();
            float tot = 0.f;
#pragma unroll
            for (int s = 0; s < TS; s++) tot += s_e[s];
            if (tid < 256) {
                int u = (blk & 3) * 256 + tid;
                float a = 0.f;
#pragma unroll 8
                for (int s = 0; s < TS; s++)
                    a += s_e[s] * mem[((size_t)b*TS + s)*UU + u];
                ctx[b*UU + u] = a / tot;
            }
        }
        grid_sync(tgt);
        // ---- attn = [h;ctx] @ Wa : block = (kq 0..3) x (ct 0..31) ----
        {
            const int ct = blk & 31, kq = blk >> 5;
#pragma unroll
            for (int i = 0; i < 4; i++) {
                int e = tid + i * NTHR;         // 4096 float4
                int r = e >> 7, k4 = e & 127;
                int ka4 = kq*128 + k4;
                float4 v = (ka4 < 256)
                    ? *reinterpret_cast<const float4*>(hd  + r*UU + ka4*4)
                    : *reinterpret_cast<const float4*>(ctx + r*UU + (ka4-256)*4);
                int kgi = k4 >> 4, kk = (k4 & 15) * 4;
                *reinterpret_cast<float4*>(&hs[(kgi*32 + r)*HP_STR + kk]) = v;
            }
            __syncthreads();
            float pa[2][4] = {{0,0,0,0},{0,0,0,0}};
            const float* hsg = &hs[(kg*32)*HP_STR];
            const int r  = lane >> 2;
            const int bc = ct*32 + nw*8 + (lane >> 2);
#pragma unroll
            for (int k8 = 0; k8 < 8; k8++) {
                int kk = k8*8 + (lane & 3);
                uint32_t a0[4], a1[4];
                a0[0] = f2tf(hsg[ r      *HP_STR + kk]);   a0[1] = f2tf(hsg[(r+ 8)*HP_STR + kk]);
                a0[2] = f2tf(hsg[ r      *HP_STR + kk+4]); a0[3] = f2tf(hsg[(r+ 8)*HP_STR + kk+4]);
                a1[0] = f2tf(hsg[(r+16)*HP_STR + kk]);     a1[1] = f2tf(hsg[(r+24)*HP_STR + kk]);
                a1[2] = f2tf(hsg[(r+16)*HP_STR + kk+4]);   a1[3] = f2tf(hsg[(r+24)*HP_STR + kk+4]);
                int krow = kq*512 + kg*64 + k8*8 + (lane & 3);
                uint32_t b0 = f2tf(Wa[(size_t)krow     * UU + bc]);
                uint32_t b1 = f2tf(Wa[(size_t)(krow+4) * UU + bc]);
                MMA_TF32(pa[0][0],pa[0][1],pa[0][2],pa[0][3],
                         a0[0],a0[1],a0[2],a0[3], b0,b1);
                MMA_TF32(pa[1][0],pa[1][1],pa[1][2],pa[1][3],
                         a1[0],a1[1],a1[2],a1[3], b0,b1);
            }
            __syncthreads();
            acc_to_zr(zr, kg, nw, lane, pa);
            __syncthreads();
            { int r2 = tid >> 5, cc = tid & 31;
              float s = 0.f;
#pragma unroll
              for (int q = 0; q < 8; q++) s += zr[(q*32 + r2)*ZR_STR + cc];
              pab[((size_t)kq*BB + r2)*UU + ct*32 + cc] = s; }
        }
        grid_sync(tgt);
        // ---- reduce partials -> attn, attnAll ----
        if (tid < 256) {
            int g = blk*256 + tid, b = g >> 10, u = g & 1023;
            float v = pab[((size_t)0*BB + b)*UU + u] + pab[((size_t)1*BB + b)*UU + u]
                    + pab[((size_t)2*BB + b)*UU + u] + pab[((size_t)3*BB + b)*UU + u];
            attn[g] = v;
            attnAll[((size_t)t*BB + b)*UU + u] = v;
        }
        grid_sync(tgt);
    }
}

// ---------------- embedding-gathered pre GEMM (one-shot) ----------------
__global__ void __launch_bounds__(128) pre_gemm(const int* __restrict__ ids, int T,
                                                const float* __restrict__ emb,
                                                const float* __restrict__ W,
                                                const float* __restrict__ bias,
                                                float* __restrict__ out) {
    __shared__ __align__(16) float As[32*36];
    __shared__ int sid[32];
    const int tid = threadIdx.x;
    const int t   = blockIdx.y;
    const int col = blockIdx.x * 128 + tid;
    if (tid < 32) sid[tid] = ids[tid * T + t];
    __syncthreads();
    float acc[32];
#pragma unroll
    for (int r = 0; r < 32; r++) acc[r] = 0.f;
    for (int kk = 0; kk < EE; kk += 32) {
#pragma unroll
        for (int i = 0; i < 8; i++) {
            int e = tid + i * 128;
            int j = e & 31, r = e >> 5;
            As[j*36 + r] = emb[sid[r]*EE + kk + j];
        }
        __syncthreads();
#pragma unroll 4
        for (int j = 0; j < 32; j++) {
            float w = W[(kk + j) * G4 + col];
#pragma unroll
            for (int q = 0; q < 8; q++) {
                float4 a = *reinterpret_cast<const float4*>(&As[j*36 + q*4]);
                acc[q*4+0] += a.x*w; acc[q*4+1] += a.y*w;
                acc[q*4+2] += a.z*w; acc[q*4+3] += a.w*w;
            }
        }
        __syncthreads();
    }
    float bb = bias[col];
    float* o = out + t * 32 * G4 + col;
#pragma unroll
    for (int r = 0; r < 32; r++) o[r * G4] = acc[r] + bb;
}

// ---------------- full-K skinny GEMM (keys, one-shot) ----------------
__global__ void __launch_bounds__(128) fullk32_gemm(const float* __restrict__ A_,
                                                    const float* __restrict__ W,
                                                    float* __restrict__ out, int N) {
    __shared__ __align__(16) float As[32*36];
    const int tid = threadIdx.x;
    const int col = blockIdx.x * 128 + tid;
    const float* A = A_ + (size_t)blockIdx.y * 32 * UU;
    float acc[32];
#pragma unroll
    for (int r = 0; r < 32; r++) acc[r] = 0.f;
    for (int kk = 0; kk < UU; kk += 32) {
#pragma unroll
        for (int i = 0; i < 8; i++) {
            int e = tid + i * 128;
            int j = e & 31, r = e >> 5;
            As[j*36 + r] = A[r * UU + kk + j];
        }
        __syncthreads();
#pragma unroll 4
        for (int j = 0; j < 32; j++) {
            float w = W[(kk + j) * N + col];
#pragma unroll
            for (int q = 0; q < 8; q++) {
                float4 a = *reinterpret_cast<const float4*>(&As[j*36 + q*4]);
                acc[q*4+0] += a.x*w; acc[q*4+1] += a.y*w;
                acc[q*4+2] += a.z*w; acc[q*4+3] += a.w*w;
            }
        }
        __syncthreads();
    }
    float* o = out + (size_t)blockIdx.y * 32 * N + col;
#pragma unroll
    for (int r = 0; r < 32; r++) o[r * N] = acc[r];
}

// ---------------- final logits GEMM: tf32 mma, 128x128 tile ----------------
#define KC 32
__global__ void __launch_bounds__(256) final_mma(const float* __restrict__ A,
                                                 const float* __restrict__ Wf,
                                                 const float* __restrict__ bf,
                                                 float* __restrict__ out) {
    const int m0 = blockIdx.x * 128;
    const int n0 = blockIdx.y * 128;
    const int tid = threadIdx.x, lane = tid & 31, warp = tid >> 5;
    const int wm = warp >> 1;
    const int wn = warp & 1;
    __shared__ uint32_t Asm[128][KC + 1];
    __shared__ uint32_t Bsm[KC][128 + 8];
    float acc[2][8][4];
#pragma unroll
    for (int mi = 0; mi < 2; mi++)
#pragma unroll
        for (int nf = 0; nf < 8; nf++)
#pragma unroll
            for (int i = 0; i < 4; i++) acc[mi][nf][i] = 0.f;

    for (int k0 = 0; k0 < UU; k0 += KC) {
#pragma unroll
        for (int i = 0; i < 4; i++) {
            int e = tid + i * 256;
            int r = e >> 3, c = (e & 7) * 4;
            float4 v = *reinterpret_cast<const float4*>(A + (size_t)(m0 + r) * UU + k0 + c);
            Asm[r][c] = f2tf(v.x); Asm[r][c+1] = f2tf(v.y);
            Asm[r][c+2] = f2tf(v.z); Asm[r][c+3] = f2tf(v.w);
        }
#pragma unroll
        for (int i = 0; i < 4; i++) {
            int e = tid + i * 256;
            int r = e >> 5, c = (e & 31) * 4;
            float4 v = *reinterpret_cast<const float4*>(Wf + (size_t)(k0 + r) * VT + n0 + c);
            Bsm[r][c] = f2tf(v.x); Bsm[r][c+1] = f2tf(v.y);
            Bsm[r][c+2] = f2tf(v.z); Bsm[r][c+3] = f2tf(v.w);
        }
        __syncthreads();
#pragma unroll
        for (int k8 = 0; k8 < 4; k8++) {
            const int kb = k8 * 8;
            uint32_t af[2][4];
#pragma unroll
            for (int mi = 0; mi < 2; mi++) {
                int ar = 32 * wm + 16 * mi + (lane >> 2);
                int ac = kb + (lane & 3);
                af[mi][0] = Asm[ar][ac];     af[mi][1] = Asm[ar + 8][ac];
                af[mi][2] = Asm[ar][ac + 4]; af[mi][3] = Asm[ar + 8][ac + 4];
            }
#pragma unroll
            for (int nf = 0; nf < 8; nf++) {
                int bc = 64 * wn + nf * 8 + (lane >> 2);
                int br = kb + (lane & 3);
                uint32_t b0 = Bsm[br][bc], b1 = Bsm[br + 4][bc];
#pragma unroll
                for (int mi = 0; mi < 2; mi++) {
                    MMA_TF32(acc[mi][nf][0], acc[mi][nf][1], acc[mi][nf][2], acc[mi][nf][3],
                             af[mi][0], af[mi][1], af[mi][2], af[mi][3], b0, b1);
                }
            }
        }
        __syncthreads();
    }
#pragma unroll
    for (int mi = 0; mi < 2; mi++) {
#pragma unroll
        for (int nf = 0; nf < 8; nf++) {
            int col = n0 + 64 * wn + nf * 8 + (lane & 3) * 2;
            float bb0 = bf[col], bb1 = bf[col + 1];
#pragma unroll
            for (int hh = 0; hh < 2; hh++) {
                int m = m0 + 32 * wm + 16 * mi + (lane >> 2) + 8 * hh;
                if (m < TD * BB) {
                    int b = m & 31, t = m >> 5;
                    float* o = out + ((size_t)(b * TD + t)) * VT + col;
                    o[0] = acc[mi][nf][2*hh + 0] + bb0;
                    o[1] = acc[mi][nf][2*hh + 1] + bb1;
                }
            }
        }
    }
}

// ---------------- host ----------------
extern "C" void kernel_launch(void* const* d_in, const int* in_sizes, int n_in,
                              void* d_out, int out_size) {
    const int*   enc_in  = (const int*)  d_in[0];
    const int*   dec_in  = (const int*)  d_in[1];
    const float* enc_emb = (const float*)d_in[2];
    const float* dec_emb = (const float*)d_in[3];
    const float* Wx_e    = (const float*)d_in[4];
    const float* Wh_e    = (const float*)d_in[5];
    const float* b_e     = (const float*)d_in[6];
    const float* Wx_d    = (const float*)d_in[7];
    const float* Wh_d    = (const float*)d_in[8];
    const float* b_d     = (const float*)d_in[9];
    const float* Wm      = (const float*)d_in[10];
    const float* Wa      = (const float*)d_in[11];
    const float* Wf      = (const float*)d_in[12];
    const float* bf      = (const float*)d_in[13];
    float* out = (float*)d_out;

    float *pEncPre, *pDecPre, *pMem, *pKeys, *pHe, *pCe, *pHd, *pCd;
    float *pAttn, *pCtx, *pScore, *pZ, *pPab, *pAll;
    cudaGetSymbolAddress((void**)&pEncPre, g_EncPre);
    cudaGetSymbolAddress((void**)&pDecPre, g_DecPre);
    cudaGetSymbolAddress((void**)&pMem,    g_mem);
    cudaGetSymbolAddress((void**)&pKeys,   g_keys);
    cudaGetSymbolAddress((void**)&pHe,     g_he);
    cudaGetSymbolAddress((void**)&pCe,     g_ce);
    cudaGetSymbolAddress((void**)&pHd,     g_hd);
    cudaGetSymbolAddress((void**)&pCd,     g_cd);
    cudaGetSymbolAddress((void**)&pAttn,   g_attn);
    cudaGetSymbolAddress((void**)&pCtx,    g_ctx);
    cudaGetSymbolAddress((void**)&pScore,  g_score);
    cudaGetSymbolAddress((void**)&pZ,      g_z);
    cudaGetSymbolAddress((void**)&pPab,    g_pab);
    cudaGetSymbolAddress((void**)&pAll,    g_attnAll);

    cudaFuncSetAttribute(enc_persistent, cudaFuncAttributeMaxDynamicSharedMemorySize, SMEM_BYTES);
    cudaFuncSetAttribute(dec_persistent, cudaFuncAttributeMaxDynamicSharedMemorySize, SMEM_BYTES);

    // one-shot input projections
    pre_gemm<<<dim3(32, TS), 128>>>(enc_in, TS, enc_emb, Wx_e, b_e, pEncPre);
    pre_gemm<<<dim3(32, TD), 128>>>(dec_in, TD, dec_emb, Wx_d, b_d, pDecPre);

    // persistent encoder recurrence
    enc_persistent<<<GRID, NTHR, SMEM_BYTES>>>(pEncPre, Wh_e, pHe, pCe, pMem, pZ);

    // attention keys
    fullk32_gemm<<<dim3(8, 64), 128>>>(pMem, Wm, pKeys, UU);

    // persistent decoder recurrence
    dec_persistent<<<GRID, NTHR, SMEM_BYTES>>>(pDecPre, Wh_d, Wx_d + 256*G4, Wa,
                                               pKeys, pMem, pHe, pCe, pHd, pCd,
                                               pAttn, pCtx, pScore, pZ, pPab, pAll);

    // batched logits GEMM
    final_mma<<<dim3(16, VT / 128), 256>>>(pAll, Wf, bf, out);
}